// round 3
// baseline (speedup 1.0000x reference)
#include <cuda_runtime.h>

#define NN 8192
#define ROWS_PER_BLK 8
#define MV_THREADS 256   // 8 warps, one row per warp

// Scratch (allocation-free rule: __device__ globals)
__device__ float g_conv[NN];
__device__ float g_h[NN];

// Kernel 1: per-node 16-wide dot + bias + sigmoid. 64-thread blocks to
// spread across SMs (latency-bound: 4 float4 loads per thread).
__global__ void __launch_bounds__(64) conv_sigmoid_kernel(
    const float* __restrict__ nf,
    const float* __restrict__ cw,
    const float* __restrict__ cb) {
    int i = blockIdx.x * 64 + threadIdx.x;
    if (i >= NN) return;
    const float4* row = reinterpret_cast<const float4*>(nf + (size_t)i * 16);
    float4 w0 = reinterpret_cast<const float4*>(cw)[0];
    float4 w1 = reinterpret_cast<const float4*>(cw)[1];
    float4 w2 = reinterpret_cast<const float4*>(cw)[2];
    float4 w3 = reinterpret_cast<const float4*>(cw)[3];
    float4 a0 = row[0], a1 = row[1], a2 = row[2], a3 = row[3];
    float s = a0.x*w0.x + a0.y*w0.y + a0.z*w0.z + a0.w*w0.w
            + a1.x*w1.x + a1.y*w1.y + a1.z*w1.z + a1.w*w1.w
            + a2.x*w2.x + a2.y*w2.y + a2.z*w2.z + a2.w*w2.w
            + a3.x*w3.x + a3.y*w3.y + a3.z*w3.z + a3.w*w3.w;
    s += cb[0];
    g_conv[i] = 1.0f / (1.0f + __expf(-s));
}

// Kernel 2/3: warp-per-row matvec with x staged in shared memory once per
// block (8 rows share one 32KB x tile -> 8x less L2 traffic for x).
template <int APPLY_TANH>
__global__ void __launch_bounds__(MV_THREADS) matvec_kernel(
    const float* __restrict__ W,
    const float* __restrict__ b,
    const float* __restrict__ x,
    float* __restrict__ y) {
    __shared__ float4 xs4[NN / 4];  // 32 KB

    const int tid  = threadIdx.x;
    const int lane = tid & 31;
    const int warp = tid >> 5;

    // Stage x into shared: 2048 float4, 256 threads -> 8 each
    const float4* __restrict__ x4 = reinterpret_cast<const float4*>(x);
    #pragma unroll
    for (int it = 0; it < (NN / 4) / MV_THREADS; ++it)
        xs4[it * MV_THREADS + tid] = x4[it * MV_THREADS + tid];
    __syncthreads();

    const int row = blockIdx.x * ROWS_PER_BLK + warp;
    const float4* __restrict__ W4 = reinterpret_cast<const float4*>(W + (size_t)row * NN);

    // 2048 float4 per row / 32 lanes = 64 per lane
    float s0 = 0.0f, s1 = 0.0f;
    #pragma unroll 8
    for (int k = 0; k < 64; k += 2) {
        int i0 = lane + 32 * k;
        int i1 = lane + 32 * (k + 1);
        float4 a0 = W4[i0];
        float4 v0 = xs4[i0];
        float4 a1 = W4[i1];
        float4 v1 = xs4[i1];
        s0 += a0.x * v0.x + a0.y * v0.y + a0.z * v0.z + a0.w * v0.w;
        s1 += a1.x * v1.x + a1.y * v1.y + a1.z * v1.z + a1.w * v1.w;
    }
    float s = s0 + s1;

    #pragma unroll
    for (int o = 16; o > 0; o >>= 1) s += __shfl_xor_sync(0xffffffffu, s, o);

    if (lane == 0) {
        s += b[row];
        y[row] = APPLY_TANH ? tanhf(s) : s;
    }
}

extern "C" void kernel_launch(void* const* d_in, const int* in_sizes, int n_in,
                              void* d_out, int out_size) {
    const float* node_features = (const float*)d_in[0]; // (8192, 16)
    const float* conv_w        = (const float*)d_in[1]; // (16,)
    const float* conv_b        = (const float*)d_in[2]; // scalar
    const float* W1            = (const float*)d_in[3]; // (8192, 8192)
    const float* b1            = (const float*)d_in[4]; // (8192,)
    const float* W2            = (const float*)d_in[5]; // (8192, 8192)
    const float* b2            = (const float*)d_in[6]; // (8192,)
    float* out = (float*)d_out;

    float* conv_feats;
    float* h;
    cudaGetSymbolAddress((void**)&conv_feats, g_conv);
    cudaGetSymbolAddress((void**)&h, g_h);

    conv_sigmoid_kernel<<<NN / 64, 64>>>(node_features, conv_w, conv_b);
    matvec_kernel<1><<<NN / ROWS_PER_BLK, MV_THREADS>>>(W1, b1, conv_feats, h);
    matvec_kernel<0><<<NN / ROWS_PER_BLK, MV_THREADS>>>(W2, b2, h, out);
}